// round 13
// baseline (speedup 1.0000x reference)
#include <cuda_runtime.h>
#include <cstdint>

// ---------------- tile / pipeline config ----------------
#define CTA_M    128
#define CTA_N    128          // cols [0,80): IMMA warps, cols [80,128): dp4a warps
#define N_IMMA   80
#define K_STAGE  128
#define STAGES   4            // 4 buffers; producers run 3 ahead
#define CTA_THREADS 256       // warps 0-3: dp4a + producer, warps 4-7: IMMA (pipelined)

#define A_BYTES      (CTA_M * K_STAGE)                 // 16384
#define STAGE_BYTES  ((CTA_M + CTA_N) * K_STAGE)       // 32768
#define SMEM_TOTAL   (STAGES * STAGE_BYTES)            // 131072 -> occ 1, 255 regs

#define MAXM 8192
#define MAXN 4096
#define MAXK 4096

__device__ __align__(16) int8_t g_X8[(size_t)MAXM * MAXK];   // 32 MB
__device__ __align__(16) int8_t g_W8[(size_t)MAXN * MAXK];   // 16 MB
__device__ int g_mode;   // 0 = raw int8, 1 = int32-promoted, 2 = float32-promoted

// ---------------- PTX helpers ----------------
__device__ __forceinline__ uint32_t smem_u32(const void* p) {
    uint32_t a;
    asm("{ .reg .u64 t; cvta.to.shared.u64 t, %1; cvt.u32.u64 %0, t; }"
        : "=r"(a) : "l"(p));
    return a;
}
__device__ __forceinline__ uint32_t sw128(uint32_t o) { return o ^ ((o >> 3) & 0x70); }

__device__ __forceinline__ void cp16(uint32_t dst, const void* src) {
    asm volatile("cp.async.cg.shared.global [%0], [%1], 16;"
                 :: "r"(dst), "l"(src) : "memory");
}
__device__ __forceinline__ void cp_commit() {
    asm volatile("cp.async.commit_group;" ::: "memory");
}
template <int N>
__device__ __forceinline__ void cp_wait() {
    asm volatile("cp.async.wait_group %0;" :: "n"(N) : "memory");
}
__device__ __forceinline__ void ldsm_x4(uint32_t* r, uint32_t addr) {
    asm volatile("ldmatrix.sync.aligned.m8n8.x4.shared.b16 {%0,%1,%2,%3}, [%4];"
                 : "=r"(r[0]), "=r"(r[1]), "=r"(r[2]), "=r"(r[3])
                 : "r"(addr));
}
__device__ __forceinline__ void ldsm_x2(uint32_t* r, uint32_t addr) {
    asm volatile("ldmatrix.sync.aligned.m8n8.x2.shared.b16 {%0,%1}, [%2];"
                 : "=r"(r[0]), "=r"(r[1])
                 : "r"(addr));
}
__device__ __forceinline__ void mma_s8(int* c, const uint32_t* a, const uint32_t* b) {
    asm volatile(
        "mma.sync.aligned.m16n8k32.row.col.s32.s8.s8.s32 "
        "{%0,%1,%2,%3}, {%4,%5,%6,%7}, {%8,%9}, {%0,%1,%2,%3};"
        : "+r"(c[0]), "+r"(c[1]), "+r"(c[2]), "+r"(c[3])
        : "r"(a[0]), "r"(a[1]), "r"(a[2]), "r"(a[3]),
          "r"(b[0]), "r"(b[1]));
}
__device__ __forceinline__ int dp4a(int a, int b, int c) {
    int d;
    asm("dp4a.s32.s32 %0, %1, %2, %3;" : "=r"(d) : "r"(a), "r"(b), "r"(c));
    return d;
}
__device__ __forceinline__ int4 lds128(const char* p) {
    return *reinterpret_cast<const int4*>(p);
}

// ---------------- dtype detection ----------------
__global__ void detect_kernel(const void* __restrict__ x, long n_elems) {
    __shared__ int s_i32ok, s_f32ok;
    if (threadIdx.x == 0) { s_i32ok = 1; s_f32ok = 1; }
    __syncthreads();
    const int*   xi = (const int*)x;
    const float* xf = (const float*)x;
    const long max_words = n_elems / 4;
    const long stride = max_words / (256 * 64);
    int i32ok = 1, f32ok = 1;
    for (int j = 0; j < 64; j++) {
        long idx = ((long)threadIdx.x * 64 + j) * stride;
        int w = xi[idx];
        i32ok &= (w >= -128 && w <= 127);
        float f = xf[idx];
        f32ok &= (f == rintf(f)) && (fabsf(f) <= 127.0f);
    }
    if (!i32ok) atomicAnd(&s_i32ok, 0);
    if (!f32ok) atomicAnd(&s_f32ok, 0);
    __syncthreads();
    if (threadIdx.x == 0) g_mode = s_i32ok ? 1 : (s_f32ok ? 2 : 0);
}

// ---------------- convert: promoted input -> packed int8 ----------------
__global__ void convert_kernel(const void* __restrict__ src, int8_t* __restrict__ dst,
                               long n) {
    const int mode = g_mode;
    const long stride = (long)gridDim.x * blockDim.x * 16;
    for (long i = ((long)blockIdx.x * blockDim.x + threadIdx.x) * 16; i < n; i += stride) {
        int4 out;
        if (mode == 1) {
            const int4* s = (const int4*)((const int*)src + i);
            int4 v0 = s[0], v1 = s[1], v2 = s[2], v3 = s[3];
            out.x = (v0.x & 0xFF) | ((v0.y & 0xFF) << 8) | ((v0.z & 0xFF) << 16) | ((v0.w & 0xFF) << 24);
            out.y = (v1.x & 0xFF) | ((v1.y & 0xFF) << 8) | ((v1.z & 0xFF) << 16) | ((v1.w & 0xFF) << 24);
            out.z = (v2.x & 0xFF) | ((v2.y & 0xFF) << 8) | ((v2.z & 0xFF) << 16) | ((v2.w & 0xFF) << 24);
            out.w = (v3.x & 0xFF) | ((v3.y & 0xFF) << 8) | ((v3.z & 0xFF) << 16) | ((v3.w & 0xFF) << 24);
        } else if (mode == 2) {
            const float4* s = (const float4*)((const float*)src + i);
            float4 v0 = s[0], v1 = s[1], v2 = s[2], v3 = s[3];
            int4 a0 = make_int4(__float2int_rn(v0.x), __float2int_rn(v0.y),
                                __float2int_rn(v0.z), __float2int_rn(v0.w));
            int4 a1 = make_int4(__float2int_rn(v1.x), __float2int_rn(v1.y),
                                __float2int_rn(v1.z), __float2int_rn(v1.w));
            int4 a2 = make_int4(__float2int_rn(v2.x), __float2int_rn(v2.y),
                                __float2int_rn(v2.z), __float2int_rn(v2.w));
            int4 a3 = make_int4(__float2int_rn(v3.x), __float2int_rn(v3.y),
                                __float2int_rn(v3.z), __float2int_rn(v3.w));
            out.x = (a0.x & 0xFF) | ((a0.y & 0xFF) << 8) | ((a0.z & 0xFF) << 16) | ((a0.w & 0xFF) << 24);
            out.y = (a1.x & 0xFF) | ((a1.y & 0xFF) << 8) | ((a1.z & 0xFF) << 16) | ((a1.w & 0xFF) << 24);
            out.z = (a2.x & 0xFF) | ((a2.y & 0xFF) << 8) | ((a2.z & 0xFF) << 16) | ((a2.w & 0xFF) << 24);
            out.w = (a3.x & 0xFF) | ((a3.y & 0xFF) << 8) | ((a3.z & 0xFF) << 16) | ((a3.w & 0xFF) << 24);
        } else {
            out = *(const int4*)((const int8_t*)src + i);
        }
        *(int4*)(dst + i) = out;
    }
}

__device__ __forceinline__ float bias_at(const void* BIAS, int idx, int mode) {
    if (mode == 1) return (float)((const int*)BIAS)[idx];
    if (mode == 2) return ((const float*)BIAS)[idx];
    return (float)((const int8_t*)BIAS)[idx];
}

// producer (dp4a warps = tid 0..127): 16 x 16B chunks per thread per stage.
__device__ __forceinline__ void produce_stage(uint32_t base, const int8_t* xs,
                                              const int8_t* ws, int t2, int K) {
#pragma unroll
    for (int i = 0; i < 8; i++)
        cp16(base + sw128(((uint32_t)t2 + 128u * i) * 16), xs + (size_t)i * 16 * K);
#pragma unroll
    for (int i = 0; i < 8; i++)
        cp16(base + A_BYTES + sw128(((uint32_t)t2 + 128u * i) * 16), ws + (size_t)i * 16 * K);
}

// ---------------- occ-1, register-rich, frag-pipelined hybrid GEMM ----------------
// __launch_bounds__(256,1): 255 regs/thread; smem 131KB also forces 1 CTA/SM.
// IMMA warps (4-7) keep a full DOUBLE-BUFFERED fragment set: while MMAing step
// (ki,j) they preload (ki,j+1) — and at j==3 they preload (ki+1,0) BEFORE the
// stage barrier, so the tensor pipe restarts instantly after every barrier.
// Producers (dp4a warps 0-3) run 3 stages ahead (4 smem buffers); cp_wait<1>
// before the bottom barrier guarantees stage ki+2 is resident at the top of
// stage ki+1 (needed for the cross-stage preload).
__global__ void __launch_bounds__(CTA_THREADS, 1)
w8a8_linear_kernel(const int8_t* __restrict__ X, const int8_t* __restrict__ W,
                   const void* __restrict__ BIAS, const float* __restrict__ pA,
                   const float* __restrict__ pB, float* __restrict__ OUT,
                   int M, int N, int K)
{
    extern __shared__ char smem[];
    const uint32_t sb = smem_u32(smem);
    const int tid  = threadIdx.x;
    const int wid  = tid >> 5;
    const int lane = tid & 31;
    const bool isdp = (wid < 4);

    const int m_base = blockIdx.y * CTA_M;
    const int n_base = blockIdx.x * CTA_N;
    const int num_k  = K / K_STAGE;     // 32

    const float alpha = *pA;
    const float beta  = *pB;
    const int   mode  = g_mode;

    if (isdp) {
        // ============ dp4a warps (0-3): producer + fma-pipe GEMM ============
        const int t2 = tid;
        const int8_t* xsrc = X + (size_t)(m_base + (t2 >> 3)) * K + (t2 & 7) * 16;
        const int8_t* wsrc = W + (size_t)(n_base + (t2 >> 3)) * K + (t2 & 7) * 16;

        // prologue: fill stages 0,1,2 (3 groups)
#pragma unroll
        for (int s = 0; s < 3; s++) {
            produce_stage(sb + s * STAGE_BYTES, xsrc + (size_t)s * K_STAGE,
                          wsrc + (size_t)s * K_STAGE, t2, K);
            cp_commit();
        }
        cp_wait<1>();                    // stages 0,1 resident
        __syncthreads();                 // top of stage 0 (shared with IMMA preload)

        const int dwid = wid;            // 0..3, owns rows dwid*32 .. +31
        const int tm = lane >> 3;        // 0..3
        const int tn = lane & 7;         // 0..7
        const int rbase = dwid * 32 + tm;

        int acc[8][6];                   // rows tm+4i (i<8), cols tn+8j (j<6)
#pragma unroll
        for (int i = 0; i < 8; i++)
#pragma unroll
            for (int j = 0; j < 6; j++) acc[i][j] = 0;

        int buf = 0;
        for (int ki = 0; ki < num_k; ki++) {
            // produce stage ki+3 into buffer (ki+3)&3 == (ki-1)&3 (reader-free)
            if (ki + 3 < num_k) {
                const int wbuf = (ki + 3) & 3;
                produce_stage(sb + wbuf * STAGE_BYTES,
                              xsrc + (size_t)(ki + 3) * K_STAGE,
                              wsrc + (size_t)(ki + 3) * K_STAGE, t2, K);
            }
            cp_commit();                 // keep group sequence aligned

            const char* SAc = smem + buf * STAGE_BYTES;
            const char* SBc = SAc + A_BYTES;
#pragma unroll
            for (int kk = 0; kk < 8; kk++) {
                int4 av[8];
#pragma unroll
                for (int i = 0; i < 8; i++)
                    av[i] = lds128(SAc + sw128((uint32_t)(rbase + 4 * i) * 128 + kk * 16));
#pragma unroll
                for (int jj = 0; jj < 6; jj++) {
                    const int4 bv = lds128(SBc + sw128((uint32_t)(N_IMMA + tn + 8 * jj) * 128
                                                       + kk * 16));
#pragma unroll
                    for (int i = 0; i < 8; i++) {
                        int c = acc[i][jj];
                        c = dp4a(av[i].x, bv.x, c);
                        c = dp4a(av[i].y, bv.y, c);
                        c = dp4a(av[i].z, bv.z, c);
                        c = dp4a(av[i].w, bv.w, c);
                        acc[i][jj] = c;
                    }
                }
            }
            cp_wait<1>();                // all groups except newest done -> ki+2 resident
            __syncthreads();             // bottom barrier = top of stage ki+1
            buf = (buf + 1) & 3;
        }

        // epilogue: cols [80, 128)
#pragma unroll
        for (int jj = 0; jj < 6; jj++) {
            const int col = n_base + N_IMMA + tn + 8 * jj;
            const float bb = beta * bias_at(BIAS, col, mode);
#pragma unroll
            for (int i = 0; i < 8; i++) {
                const int row = m_base + rbase + 4 * i;
                int q = __float2int_rn(fmaf(alpha, (float)acc[i][jj], bb));
                q = max(-128, min(127, q));
                OUT[(size_t)row * N + col] = (float)q;
            }
        }
    } else {
        // ============ IMMA warps (4-7): frag-pipelined MMA stream ============
        const int iw    = wid - 4;
        const int warpM = iw >> 1;
        const int warpN = iw & 1;
        const int arow_l = (lane & 7) + ((lane >> 3) & 1) * 8;
        const int aoff_l = (lane >> 4) * 16;
        const int brow_l = (lane >> 4) * 8 + (lane & 7);
        const int boff_l = ((lane >> 3) & 1) * 16;
        const int brow2_l = lane & 7;
        const int boff2_l = ((lane >> 3) & 1) * 16;

        // per-slot swizzled lane addresses relative to a stage base
        const uint32_t aoffs0 = sw128((uint32_t)(warpM * 64 +  0 + arow_l) * 128 + aoff_l);
        const uint32_t aoffs1 = sw128((uint32_t)(warpM * 64 + 16 + arow_l) * 128 + aoff_l);
        const uint32_t aoffs2 = sw128((uint32_t)(warpM * 64 + 32 + arow_l) * 128 + aoff_l);
        const uint32_t aoffs3 = sw128((uint32_t)(warpM * 64 + 48 + arow_l) * 128 + aoff_l);
        const uint32_t boffs0 = sw128((uint32_t)(warpN * 40 +  0 + brow_l) * 128 + boff_l);
        const uint32_t boffs1 = sw128((uint32_t)(warpN * 40 + 16 + brow_l) * 128 + boff_l);
        const uint32_t boffs2 = sw128((uint32_t)(warpN * 40 + 32 + brow2_l) * 128 + boff2_l);
        // NOTE: sw128 only permutes bits [6:4] from bits [9:7]; adding j*32
        // (bit 5) afterwards would break the swizzle, so each j gets its own
        // full recompute below via the +j*32 inside sw128. Precompute all 4 j
        // variants instead (j*32 affects swizzled bits):
        // -> handled by loading with explicit j in the helper lambda below.

        int acc[4][5][4];                 // 80 regs
#pragma unroll
        for (int mi = 0; mi < 4; mi++)
#pragma unroll
            for (int ni = 0; ni < 5; ni++)
#pragma unroll
                for (int e = 0; e < 4; e++) acc[mi][ni][e] = 0;

        uint32_t af[2][4][4], bf[2][2][4], bq[2][2];   // frag double buffer

        // helper: load frag set for (stage base, j) into slot s
        auto load_frags = [&](uint32_t SA, uint32_t SB, int j, int s) {
            ldsm_x4(af[s][0], SA + sw128((uint32_t)(warpM * 64 +  0 + arow_l) * 128 + j * 32 + aoff_l));
            ldsm_x4(af[s][1], SA + sw128((uint32_t)(warpM * 64 + 16 + arow_l) * 128 + j * 32 + aoff_l));
            ldsm_x4(af[s][2], SA + sw128((uint32_t)(warpM * 64 + 32 + arow_l) * 128 + j * 32 + aoff_l));
            ldsm_x4(af[s][3], SA + sw128((uint32_t)(warpM * 64 + 48 + arow_l) * 128 + j * 32 + aoff_l));
            ldsm_x4(bf[s][0], SB + sw128((uint32_t)(warpN * 40 +  0 + brow_l) * 128 + j * 32 + boff_l));
            ldsm_x4(bf[s][1], SB + sw128((uint32_t)(warpN * 40 + 16 + brow_l) * 128 + j * 32 + boff_l));
            ldsm_x2(bq[s],    SB + sw128((uint32_t)(warpN * 40 + 32 + brow2_l) * 128 + j * 32 + boff2_l));
        };
        (void)aoffs0; (void)aoffs1; (void)aoffs2; (void)aoffs3;
        (void)boffs0; (void)boffs1; (void)boffs2;

        __syncthreads();                  // top of stage 0: stages 0,1 resident
        load_frags(sb, sb + A_BYTES, 0, 0);   // preload (stage0, j0)

        int buf = 0, p = 0;
        for (int ki = 0; ki < num_k; ki++) {
            const uint32_t SA = sb + buf * STAGE_BYTES;
            const uint32_t SB = SA + A_BYTES;
            const int nb = (buf + 1) & 3;
            const uint32_t SAn = sb + nb * STAGE_BYTES;
            const uint32_t SBn = SAn + A_BYTES;
#pragma unroll
            for (int j = 0; j < 4; j++) {
                // preload next step's frags into the other slot
                if (j < 3) load_frags(SA, SB, j + 1, p ^ 1);
                else       load_frags(SAn, SBn, 0, p ^ 1);   // cross-stage preload
                // MMA with current slot
#pragma unroll
                for (int mi = 0; mi < 4; mi++) {
                    mma_s8(acc[mi][0], af[p][mi], &bf[p][0][0]);
                    mma_s8(acc[mi][1], af[p][mi], &bf[p][0][2]);
                    mma_s8(acc[mi][2], af[p][mi], &bf[p][1][0]);
                    mma_s8(acc[mi][3], af[p][mi], &bf[p][1][2]);
                    mma_s8(acc[mi][4], af[p][mi], bq[p]);
                }
                p ^= 1;
            }
            __syncthreads();              // bottom barrier (pairs with dp side)
            buf = nb;
        }

        // epilogue: cols [0, 80)
#pragma unroll
        for (int mi = 0; mi < 4; mi++) {
#pragma unroll
            for (int ni = 0; ni < 5; ni++) {
                const int row0 = m_base + warpM * 64 + mi * 16 + (lane >> 2);
                const int col0 = n_base + warpN * 40 + ni * 8 + (lane & 3) * 2;
                const float bb0 = beta * bias_at(BIAS, col0, mode);
                const float bb1 = beta * bias_at(BIAS, col0 + 1, mode);
#pragma unroll
                for (int h = 0; h < 2; h++) {
                    const int row = row0 + h * 8;
                    int q0 = __float2int_rn(fmaf(alpha, (float)acc[mi][ni][2 * h],     bb0));
                    int q1 = __float2int_rn(fmaf(alpha, (float)acc[mi][ni][2 * h + 1], bb1));
                    q0 = max(-128, min(127, q0));
                    q1 = max(-128, min(127, q1));
                    *reinterpret_cast<float2*>(OUT + (size_t)row * N + col0) =
                        make_float2((float)q0, (float)q1);
                }
            }
        }
    }
}

// ---------------- launch ----------------
extern "C" void kernel_launch(void* const* d_in, const int* in_sizes, int n_in,
                              void* d_out, int out_size)
{
    const void*  x    = d_in[0];
    const void*  w    = d_in[1];
    const void*  bias = d_in[2];
    const float* a    = (const float*)d_in[3];
    const float* b    = (const float*)d_in[4];

    const int N = in_sizes[2];              // 4096
    const int K = in_sizes[1] / N;          // 4096
    const int M = in_sizes[0] / K;          // 8192

    int8_t *x8, *w8;
    cudaGetSymbolAddress((void**)&x8, g_X8);
    cudaGetSymbolAddress((void**)&w8, g_W8);

    detect_kernel<<<1, 256>>>(x, (long)in_sizes[0]);
    convert_kernel<<<4096, 256>>>(x, x8, (long)M * K);
    convert_kernel<<<4096, 256>>>(w, w8, (long)N * K);

    cudaFuncSetAttribute(w8a8_linear_kernel,
                         cudaFuncAttributeMaxDynamicSharedMemorySize, SMEM_TOTAL);
    dim3 grid(N / CTA_N, M / CTA_M);        // (32, 64)
    w8a8_linear_kernel<<<grid, CTA_THREADS, SMEM_TOTAL>>>(
        x8, w8, bias, a, b, (float*)d_out, M, N, K);
}

// round 14
// speedup vs baseline: 1.0943x; 1.0943x over previous
#include <cuda_runtime.h>
#include <cstdint>

// ---------------- tile / pipeline config ----------------
#define CTA_M    128
#define CTA_N    256          // cols [0,160): IMMA warps, cols [160,256): dp4a warps
#define N_IMMA   160
#define K_STAGE  128
#define STAGES   4            // 4 buffers; producers run 3 ahead (cross-stage preload safe)
#define CTA_THREADS 384       // warps 0-3: dp4a + producer, warps 4-11: IMMA

#define A_BYTES      (CTA_M * K_STAGE)                 // 16384
#define STAGE_BYTES  ((CTA_M + CTA_N) * K_STAGE)       // 49152
#define SMEM_TOTAL   (STAGES * STAGE_BYTES)            // 196608 -> occ 1, 170 regs

#define MAXM 8192
#define MAXN 4096
#define MAXK 4096

__device__ __align__(16) int8_t g_X8[(size_t)MAXM * MAXK];   // 32 MB
__device__ __align__(16) int8_t g_W8[(size_t)MAXN * MAXK];   // 16 MB
__device__ int g_i32ok = 1;   // sticky AND flags (deterministic across graph replays)
__device__ int g_f32ok = 1;

// ---------------- PTX helpers ----------------
__device__ __forceinline__ uint32_t smem_u32(const void* p) {
    uint32_t a;
    asm("{ .reg .u64 t; cvta.to.shared.u64 t, %1; cvt.u32.u64 %0, t; }"
        : "=r"(a) : "l"(p));
    return a;
}
__device__ __forceinline__ uint32_t sw128(uint32_t o) { return o ^ ((o >> 3) & 0x70); }

__device__ __forceinline__ void cp16(uint32_t dst, const void* src) {
    asm volatile("cp.async.cg.shared.global [%0], [%1], 16;"
                 :: "r"(dst), "l"(src) : "memory");
}
__device__ __forceinline__ void cp_commit() {
    asm volatile("cp.async.commit_group;" ::: "memory");
}
template <int N>
__device__ __forceinline__ void cp_wait() {
    asm volatile("cp.async.wait_group %0;" :: "n"(N) : "memory");
}
__device__ __forceinline__ void ldsm_x4(uint32_t* r, uint32_t addr) {
    asm volatile("ldmatrix.sync.aligned.m8n8.x4.shared.b16 {%0,%1,%2,%3}, [%4];"
                 : "=r"(r[0]), "=r"(r[1]), "=r"(r[2]), "=r"(r[3])
                 : "r"(addr));
}
__device__ __forceinline__ void ldsm_x2(uint32_t* r, uint32_t addr) {
    asm volatile("ldmatrix.sync.aligned.m8n8.x2.shared.b16 {%0,%1}, [%2];"
                 : "=r"(r[0]), "=r"(r[1])
                 : "r"(addr));
}
__device__ __forceinline__ void mma_s8(int* c, const uint32_t* a, const uint32_t* b) {
    asm volatile(
        "mma.sync.aligned.m16n8k32.row.col.s32.s8.s8.s32 "
        "{%0,%1,%2,%3}, {%4,%5,%6,%7}, {%8,%9}, {%0,%1,%2,%3};"
        : "+r"(c[0]), "+r"(c[1]), "+r"(c[2]), "+r"(c[3])
        : "r"(a[0]), "r"(a[1]), "r"(a[2]), "r"(a[3]),
          "r"(b[0]), "r"(b[1]));
}
__device__ __forceinline__ int dp4a(int a, int b, int c) {
    int d;
    asm("dp4a.s32.s32 %0, %1, %2, %3;" : "=r"(d) : "r"(a), "r"(b), "r"(c));
    return d;
}
__device__ __forceinline__ int4 lds128(const char* p) {
    return *reinterpret_cast<const int4*>(p);
}
__device__ __forceinline__ int get_mode() {
    return g_i32ok ? 1 : (g_f32ok ? 2 : 0);
}

// ---------------- dtype detection (parallel, sticky-AND flags) ----------------
__global__ void detect_kernel(const void* __restrict__ x, long n_elems) {
    const int*   xi = (const int*)x;
    const float* xf = (const float*)x;
    const long max_words = n_elems / 4;           // safe even if data is raw int8
    const long total = (long)gridDim.x * blockDim.x;
    const long stride = max_words / (2 * total);
    const long g = (long)blockIdx.x * blockDim.x + threadIdx.x;
    int i32ok = 1, f32ok = 1;
#pragma unroll
    for (int j = 0; j < 2; j++) {
        long idx = (g * 2 + j) * stride;
        int w = xi[idx];
        i32ok &= (w >= -128 && w <= 127);
        float f = xf[idx];
        f32ok &= (f == rintf(f)) && (fabsf(f) <= 127.0f);
    }
    // warp-level reduce, one atomic per failing warp
    const unsigned m = 0xFFFFFFFFu;
    bool all_i = __all_sync(m, i32ok);
    bool all_f = __all_sync(m, f32ok);
    if ((threadIdx.x & 31) == 0) {
        if (!all_i) atomicAnd(&g_i32ok, 0);
        if (!all_f) atomicAnd(&g_f32ok, 0);
    }
}

// ---------------- convert: promoted input -> packed int8 ----------------
__global__ void convert_kernel(const void* __restrict__ src, int8_t* __restrict__ dst,
                               long n) {
    const int mode = get_mode();
    const long stride = (long)gridDim.x * blockDim.x * 16;
    for (long i = ((long)blockIdx.x * blockDim.x + threadIdx.x) * 16; i < n; i += stride) {
        int4 out;
        if (mode == 1) {
            const int4* s = (const int4*)((const int*)src + i);
            int4 v0 = s[0], v1 = s[1], v2 = s[2], v3 = s[3];
            out.x = (v0.x & 0xFF) | ((v0.y & 0xFF) << 8) | ((v0.z & 0xFF) << 16) | ((v0.w & 0xFF) << 24);
            out.y = (v1.x & 0xFF) | ((v1.y & 0xFF) << 8) | ((v1.z & 0xFF) << 16) | ((v1.w & 0xFF) << 24);
            out.z = (v2.x & 0xFF) | ((v2.y & 0xFF) << 8) | ((v2.z & 0xFF) << 16) | ((v2.w & 0xFF) << 24);
            out.w = (v3.x & 0xFF) | ((v3.y & 0xFF) << 8) | ((v3.z & 0xFF) << 16) | ((v3.w & 0xFF) << 24);
        } else if (mode == 2) {
            const float4* s = (const float4*)((const float*)src + i);
            float4 v0 = s[0], v1 = s[1], v2 = s[2], v3 = s[3];
            int4 a0 = make_int4(__float2int_rn(v0.x), __float2int_rn(v0.y),
                                __float2int_rn(v0.z), __float2int_rn(v0.w));
            int4 a1 = make_int4(__float2int_rn(v1.x), __float2int_rn(v1.y),
                                __float2int_rn(v1.z), __float2int_rn(v1.w));
            int4 a2 = make_int4(__float2int_rn(v2.x), __float2int_rn(v2.y),
                                __float2int_rn(v2.z), __float2int_rn(v2.w));
            int4 a3 = make_int4(__float2int_rn(v3.x), __float2int_rn(v3.y),
                                __float2int_rn(v3.z), __float2int_rn(v3.w));
            out.x = (a0.x & 0xFF) | ((a0.y & 0xFF) << 8) | ((a0.z & 0xFF) << 16) | ((a0.w & 0xFF) << 24);
            out.y = (a1.x & 0xFF) | ((a1.y & 0xFF) << 8) | ((a1.z & 0xFF) << 16) | ((a1.w & 0xFF) << 24);
            out.z = (a2.x & 0xFF) | ((a2.y & 0xFF) << 8) | ((a2.z & 0xFF) << 16) | ((a2.w & 0xFF) << 24);
            out.w = (a3.x & 0xFF) | ((a3.y & 0xFF) << 8) | ((a3.z & 0xFF) << 16) | ((a3.w & 0xFF) << 24);
        } else {
            out = *(const int4*)((const int8_t*)src + i);
        }
        *(int4*)(dst + i) = out;
    }
}

__device__ __forceinline__ float bias_at(const void* BIAS, int idx, int mode) {
    if (mode == 1) return (float)((const int*)BIAS)[idx];
    if (mode == 2) return ((const float*)BIAS)[idx];
    return (float)((const int8_t*)BIAS)[idx];
}

// producer (dp4a warps = tid 0..127): 24 x 16B chunks per thread per stage.
// A: 1024 chunks (8/thread), B: 2048 chunks (16/thread).
__device__ __forceinline__ void produce_stage(uint32_t base, const int8_t* xs,
                                              const int8_t* ws, int t2, int K) {
#pragma unroll
    for (int i = 0; i < 8; i++)
        cp16(base + sw128(((uint32_t)t2 + 128u * i) * 16), xs + (size_t)i * 16 * K);
#pragma unroll
    for (int i = 0; i < 16; i++)
        cp16(base + A_BYTES + sw128(((uint32_t)t2 + 128u * i) * 16), ws + (size_t)i * 16 * K);
}

// ---------------- 384-thread occ-1 hybrid GEMM (128x256 CTA) ----------------
// 12 warps/SM (R6-proven count for latency hiding) + 170 regs/thread
// (R13-proven frag double-buffering without spills).
//   Warps 0-3:  dp4a + all cp.async production. Cols [160,256), 32 rows each.
//   Warps 4-11: IMMA, 2x4 grid of 64x40 tiles over cols [0,160), with full
//               fragment double-buffer + cross-stage preload: the tensor pipe
//               restarts with zero LDSM exposure after every stage barrier.
// STAGES=4: producers run 3 ahead; cp_wait<1> at the bottom of iter ki-1
// guarantees stage ki+1 is resident throughout iter ki (preload-safe).
__global__ void __launch_bounds__(CTA_THREADS, 1)
w8a8_linear_kernel(const int8_t* __restrict__ X, const int8_t* __restrict__ W,
                   const void* __restrict__ BIAS, const float* __restrict__ pA,
                   const float* __restrict__ pB, float* __restrict__ OUT,
                   int M, int N, int K)
{
    extern __shared__ char smem[];
    const uint32_t sb = smem_u32(smem);
    const int tid  = threadIdx.x;
    const int wid  = tid >> 5;
    const int lane = tid & 31;
    const bool isdp = (wid < 4);

    const int m_base = blockIdx.y * CTA_M;
    const int n_base = blockIdx.x * CTA_N;
    const int num_k  = K / K_STAGE;     // 32

    const float alpha = *pA;
    const float beta  = *pB;
    const int   mode  = get_mode();

    if (isdp) {
        // ============ dp4a warps (0-3): producer + fma-pipe GEMM ============
        const int t2 = tid;
        const int8_t* xsrc = X + (size_t)(m_base + (t2 >> 3)) * K + (t2 & 7) * 16;
        const int8_t* wsrc = W + (size_t)(n_base + (t2 >> 3)) * K + (t2 & 7) * 16;

        // prologue: fill stages 0,1,2
#pragma unroll
        for (int s = 0; s < 3; s++) {
            produce_stage(sb + s * STAGE_BYTES, xsrc + (size_t)s * K_STAGE,
                          wsrc + (size_t)s * K_STAGE, t2, K);
            cp_commit();
        }
        cp_wait<1>();                    // stages 0,1 resident
        __syncthreads();                 // top of stage 0

        const int dwid = wid;            // 0..3, owns rows dwid*32 .. +31
        const int tm = lane >> 3;        // 0..3
        const int tn = lane & 7;         // 0..7
        const int rbase = dwid * 32 + tm;

        int acc[8][12];                  // rows tm+4i (i<8), cols tn+8j (j<12): 96 regs
#pragma unroll
        for (int i = 0; i < 8; i++)
#pragma unroll
            for (int j = 0; j < 12; j++) acc[i][j] = 0;

        int buf = 0;
        for (int ki = 0; ki < num_k; ki++) {
            // produce stage ki+3 into buffer (ki+3)&3 == (ki-1)&3 (reader-free)
            if (ki + 3 < num_k) {
                const int wbuf = (ki + 3) & 3;
                produce_stage(sb + wbuf * STAGE_BYTES,
                              xsrc + (size_t)(ki + 3) * K_STAGE,
                              wsrc + (size_t)(ki + 3) * K_STAGE, t2, K);
            }
            cp_commit();                 // keep group sequence aligned

            const char* SAc = smem + buf * STAGE_BYTES;
            const char* SBc = SAc + A_BYTES;
#pragma unroll
            for (int kk = 0; kk < 8; kk++) {
                int4 av[8];
#pragma unroll
                for (int i = 0; i < 8; i++)  // 4 distinct rows x 8-way bcast, conflict-free
                    av[i] = lds128(SAc + sw128((uint32_t)(rbase + 4 * i) * 128 + kk * 16));
#pragma unroll
                for (int jj = 0; jj < 12; jj++) {
                    // B rows 160+tn+8jj: 8 distinct rows x 4-way bcast, conflict-free
                    const int4 bv = lds128(SBc + sw128((uint32_t)(N_IMMA + tn + 8 * jj) * 128
                                                       + kk * 16));
#pragma unroll
                    for (int i = 0; i < 8; i++) {
                        int c = acc[i][jj];
                        c = dp4a(av[i].x, bv.x, c);
                        c = dp4a(av[i].y, bv.y, c);
                        c = dp4a(av[i].z, bv.z, c);
                        c = dp4a(av[i].w, bv.w, c);
                        acc[i][jj] = c;
                    }
                }
            }
            cp_wait<1>();                // all except newest group done -> ki+2 resident
            __syncthreads();             // bottom barrier = top of stage ki+1
            buf = (buf + 1) & 3;
        }

        // epilogue: cols [160, 256)
#pragma unroll
        for (int jj = 0; jj < 12; jj++) {
            const int col = n_base + N_IMMA + tn + 8 * jj;
            const float bb = beta * bias_at(BIAS, col, mode);
#pragma unroll
            for (int i = 0; i < 8; i++) {
                const int row = m_base + rbase + 4 * i;
                int q = __float2int_rn(fmaf(alpha, (float)acc[i][jj], bb));
                q = max(-128, min(127, q));
                OUT[(size_t)row * N + col] = (float)q;
            }
        }
    } else {
        // ============ IMMA warps (4-11): frag-pipelined MMA stream ============
        const int iw    = wid - 4;           // 0..7
        const int warpM = iw >> 2;           // 0..1
        const int warpN = iw & 3;            // 0..3
        const int arow_l = (lane & 7) + ((lane >> 3) & 1) * 8;
        const int aoff_l = (lane >> 4) * 16;
        const int brow_l = (lane >> 4) * 8 + (lane & 7);
        const int boff_l = ((lane >> 3) & 1) * 16;
        const int brow2_l = lane & 7;
        const int boff2_l = ((lane >> 3) & 1) * 16;

        int acc[4][5][4];                 // 80 regs
#pragma unroll
        for (int mi = 0; mi < 4; mi++)
#pragma unroll
            for (int ni = 0; ni < 5; ni++)
#pragma unroll
                for (int e = 0; e < 4; e++) acc[mi][ni][e] = 0;

        uint32_t af[2][4][4], bf[2][2][4], bq[2][2];   // frag double buffer (52 regs)

        auto load_frags = [&](uint32_t SA, uint32_t SB, int j, int s) {
            ldsm_x4(af[s][0], SA + sw128((uint32_t)(warpM * 64 +  0 + arow_l) * 128 + j * 32 + aoff_l));
            ldsm_x4(af[s][1], SA + sw128((uint32_t)(warpM * 64 + 16 + arow_l) * 128 + j * 32 + aoff_l));
            ldsm_x4(af[s][2], SA + sw128((uint32_t)(warpM * 64 + 32 + arow_l) * 128 + j * 32 + aoff_l));
            ldsm_x4(af[s][3], SA + sw128((uint32_t)(warpM * 64 + 48 + arow_l) * 128 + j * 32 + aoff_l));
            ldsm_x4(bf[s][0], SB + sw128((uint32_t)(warpN * 40 +  0 + brow_l) * 128 + j * 32 + boff_l));
            ldsm_x4(bf[s][1], SB + sw128((uint32_t)(warpN * 40 + 16 + brow_l) * 128 + j * 32 + boff_l));
            ldsm_x2(bq[s],    SB + sw128((uint32_t)(warpN * 40 + 32 + brow2_l) * 128 + j * 32 + boff2_l));
        };

        __syncthreads();                  // top of stage 0: stages 0,1 resident
        load_frags(sb, sb + A_BYTES, 0, 0);

        int buf = 0, p = 0;
        for (int ki = 0; ki < num_k; ki++) {
            const uint32_t SA = sb + buf * STAGE_BYTES;
            const uint32_t SB = SA + A_BYTES;
            const int nb = (buf + 1) & 3;
            const uint32_t SAn = sb + nb * STAGE_BYTES;
            const uint32_t SBn = SAn + A_BYTES;
#pragma unroll
            for (int j = 0; j < 4; j++) {
                if (j < 3) load_frags(SA, SB, j + 1, p ^ 1);
                else       load_frags(SAn, SBn, 0, p ^ 1);   // cross-stage preload
#pragma unroll
                for (int mi = 0; mi < 4; mi++) {
                    mma_s8(acc[mi][0], af[p][mi], &bf[p][0][0]);
                    mma_s8(acc[mi][1], af[p][mi], &bf[p][0][2]);
                    mma_s8(acc[mi][2], af[p][mi], &bf[p][1][0]);
                    mma_s8(acc[mi][3], af[p][mi], &bf[p][1][2]);
                    mma_s8(acc[mi][4], af[p][mi], bq[p]);
                }
                p ^= 1;
            }
            __syncthreads();              // bottom barrier (pairs with dp side)
            buf = nb;
        }

        // epilogue: cols [0, 160)
#pragma unroll
        for (int mi = 0; mi < 4; mi++) {
#pragma unroll
            for (int ni = 0; ni < 5; ni++) {
                const int row0 = m_base + warpM * 64 + mi * 16 + (lane >> 2);
                const int col0 = n_base + warpN * 40 + ni * 8 + (lane & 3) * 2;
                const float bb0 = beta * bias_at(BIAS, col0, mode);
                const float bb1 = beta * bias_at(BIAS, col0 + 1, mode);
#pragma unroll
                for (int h = 0; h < 2; h++) {
                    const int row = row0 + h * 8;
                    int q0 = __float2int_rn(fmaf(alpha, (float)acc[mi][ni][2 * h],     bb0));
                    int q1 = __float2int_rn(fmaf(alpha, (float)acc[mi][ni][2 * h + 1], bb1));
                    q0 = max(-128, min(127, q0));
                    q1 = max(-128, min(127, q1));
                    *reinterpret_cast<float2*>(OUT + (size_t)row * N + col0) =
                        make_float2((float)q0, (float)q1);
                }
            }
        }
    }
}

// ---------------- launch ----------------
extern "C" void kernel_launch(void* const* d_in, const int* in_sizes, int n_in,
                              void* d_out, int out_size)
{
    const void*  x    = d_in[0];
    const void*  w    = d_in[1];
    const void*  bias = d_in[2];
    const float* a    = (const float*)d_in[3];
    const float* b    = (const float*)d_in[4];

    const int N = in_sizes[2];              // 4096
    const int K = in_sizes[1] / N;          // 4096
    const int M = in_sizes[0] / K;          // 8192

    int8_t *x8, *w8;
    cudaGetSymbolAddress((void**)&x8, g_X8);
    cudaGetSymbolAddress((void**)&w8, g_W8);

    detect_kernel<<<128, 256>>>(x, (long)in_sizes[0]);
    convert_kernel<<<4096, 256>>>(x, x8, (long)M * K);
    convert_kernel<<<4096, 256>>>(w, w8, (long)N * K);

    cudaFuncSetAttribute(w8a8_linear_kernel,
                         cudaFuncAttributeMaxDynamicSharedMemorySize, SMEM_TOTAL);
    dim3 grid(N / CTA_N, M / CTA_M);        // (16, 64)
    w8a8_linear_kernel<<<grid, CTA_THREADS, SMEM_TOTAL>>>(
        x8, w8, bias, a, b, (float*)d_out, M, N, K);
}